// round 2
// baseline (speedup 1.0000x reference)
#include <cuda_runtime.h>
#include <math.h>

#define N_NODES 8000
#define N_EDGES 256000
#define F0      512

// ---------------- scratch (static device allocations; no cudaMalloc) --------
__device__ float g_w    [2][N_EDGES];
__device__ float g_dinv [2][N_NODES];          // holds deg first, then rsqrt(deg)
__device__ float g_coeff[2][N_EDGES];
__device__ int   g_hist [2][N_NODES];
__device__ int   g_offs [2][N_NODES + 1];
__device__ int   g_fill [2][N_NODES];
__device__ int   g_crow [2][N_EDGES];
__device__ float g_ccoef[2][N_EDGES];
__device__ float g_t    [2][N_NODES * F0];     // GEMM output pre-aggregation
__device__ float g_h    [2][N_NODES * F0];     // X1 then X (layer outputs)
__device__ float g_m1   [2][N_NODES * 256];
__device__ float g_m2   [2][N_NODES * 128];
__device__ float g_m3   [2][N_NODES * 64];

// ---------------- edge / degree prep ----------------------------------------
__global__ void init_kernel(int g) {
    int i = blockIdx.x * blockDim.x + threadIdx.x;
    if (i < N_NODES) { g_dinv[g][i] = 1.0f; g_hist[g][i] = 0; }
}

__global__ void edge_kernel(const float* __restrict__ data,
                            const int* __restrict__ ei, int g) {
    int e = blockIdx.x * blockDim.x + threadIdx.x;
    if (e < N_EDGES) {
        int r = ei[e];
        int c = ei[N_EDGES + e];
        float v = fmaxf(data[(size_t)r * N_NODES + c], 0.0f);
        g_w[g][e] = v;
        atomicAdd(&g_dinv[g][c], v);
        atomicAdd(&g_hist[g][c], 1);
    }
}

__global__ void dinv_kernel(int g) {
    int i = blockIdx.x * blockDim.x + threadIdx.x;
    if (i < N_NODES) g_dinv[g][i] = rsqrtf(g_dinv[g][i]);   // deg >= 1 always
}

__global__ void coeff_kernel(const int* __restrict__ ei, int g) {
    int e = blockIdx.x * blockDim.x + threadIdx.x;
    if (e < N_EDGES) {
        int r = ei[e];
        int c = ei[N_EDGES + e];
        g_coeff[g][e] = g_dinv[g][r] * g_w[g][e] * g_dinv[g][c];
    }
}

// single-block exclusive scan of hist -> offs (N=8000, 1024 threads x 8)
__global__ void scan_kernel(int g) {
    __shared__ int s[1024];
    int t = threadIdx.x;
    int base = t * 8;
    int loc[8];
    int sum = 0;
#pragma unroll
    for (int j = 0; j < 8; j++) {
        int i = base + j;
        int v = (i < N_NODES) ? g_hist[g][i] : 0;
        loc[j] = sum;
        sum += v;
    }
    s[t] = sum;
    __syncthreads();
    for (int d = 1; d < 1024; d <<= 1) {
        int v = (t >= d) ? s[t - d] : 0;
        __syncthreads();
        s[t] += v;
        __syncthreads();
    }
    int cbase = s[t] - sum;   // exclusive base for this chunk
#pragma unroll
    for (int j = 0; j < 8; j++) {
        int i = base + j;
        if (i < N_NODES) {
            int o = cbase + loc[j];
            g_offs[g][i] = o;
            g_fill[g][i] = o;
        }
    }
    if (t == 0) g_offs[g][N_NODES] = N_EDGES;
}

__global__ void scatter_kernel(const int* __restrict__ ei, int g) {
    int e = blockIdx.x * blockDim.x + threadIdx.x;
    if (e < N_EDGES) {
        int c = ei[N_EDGES + e];
        int p = atomicAdd(&g_fill[g][c], 1);
        g_crow[g][p]  = ei[e];
        g_ccoef[g][p] = g_coeff[g][e];
    }
}

// ---------------- GCN aggregation: out[c,:] = sum_e coef*t[r,:] + dinv^2*t[c,:] + b, relu
__global__ void aggregate_kernel(const float* __restrict__ t,
                                 const float* __restrict__ bias,
                                 float* __restrict__ out, int g) {
    int c = blockIdx.x;
    int f = threadIdx.x * 4;                  // 128 threads * 4 = 512
    float dv = g_dinv[g][c];
    float sc = dv * dv;
    float4 v = *reinterpret_cast<const float4*>(&t[(size_t)c * F0 + f]);
    float4 acc = make_float4(v.x * sc, v.y * sc, v.z * sc, v.w * sc);
    int e0 = g_offs[g][c], e1 = g_offs[g][c + 1];
#pragma unroll 4
    for (int e = e0; e < e1; e++) {
        int   r  = g_crow[g][e];
        float cf = g_ccoef[g][e];
        float4 u = *reinterpret_cast<const float4*>(&t[(size_t)r * F0 + f]);
        acc.x += cf * u.x; acc.y += cf * u.y; acc.z += cf * u.z; acc.w += cf * u.w;
    }
    float4 b = *reinterpret_cast<const float4*>(&bias[f]);
    acc.x = fmaxf(acc.x + b.x, 0.0f);
    acc.y = fmaxf(acc.y + b.y, 0.0f);
    acc.z = fmaxf(acc.z + b.z, 0.0f);
    acc.w = fmaxf(acc.w + b.w, 0.0f);
    *reinterpret_cast<float4*>(&out[(size_t)c * F0 + f]) = acc;
}

// ---------------- generic tiled SGEMM ---------------------------------------
// C[Mn,Nn] = A[Mn,Kn] @ B   (B is [Kn,Nn] if !TRANSB, else [Nn,Kn])
// Kn % BK == 0, Nn % 4 == 0 assumed.
template <int BM, int BN, int BK, int TM, int TN, bool TRANSB, bool BIAS, bool RELU>
__global__ __launch_bounds__((BM / TM) * (BN / TN))
void gemm_kernel(const float* __restrict__ A, const float* __restrict__ B,
                 const float* __restrict__ bias, float* __restrict__ C,
                 int Mn, int Nn, int Kn) {
    constexpr int THREADS = (BM / TM) * (BN / TN);
    __shared__ float As[BK][BM];
    __shared__ float Bs[BK][BN];
    const int tid = threadIdx.x;
    const int tx = tid % (BN / TN);
    const int ty = tid / (BN / TN);
    const int m0 = blockIdx.y * BM;
    const int n0 = blockIdx.x * BN;

    float acc[TM][TN];
#pragma unroll
    for (int i = 0; i < TM; i++)
#pragma unroll
        for (int j = 0; j < TN; j++) acc[i][j] = 0.0f;

    for (int k0 = 0; k0 < Kn; k0 += BK) {
        // load A tile (BM x BK), stored transposed As[k][m]
#pragma unroll
        for (int l = tid; l < BM * BK / 4; l += THREADS) {
            int row = l / (BK / 4);
            int kq  = (l % (BK / 4)) * 4;
            float4 v = make_float4(0.f, 0.f, 0.f, 0.f);
            if (m0 + row < Mn)
                v = *reinterpret_cast<const float4*>(&A[(size_t)(m0 + row) * Kn + k0 + kq]);
            As[kq + 0][row] = v.x; As[kq + 1][row] = v.y;
            As[kq + 2][row] = v.z; As[kq + 3][row] = v.w;
        }
        if (!TRANSB) {
#pragma unroll
            for (int l = tid; l < BK * BN / 4; l += THREADS) {
                int kk = l / (BN / 4);
                int nq = (l % (BN / 4)) * 4;
                float4 v = make_float4(0.f, 0.f, 0.f, 0.f);
                if (n0 + nq < Nn)
                    v = *reinterpret_cast<const float4*>(&B[(size_t)(k0 + kk) * Nn + n0 + nq]);
                *reinterpret_cast<float4*>(&Bs[kk][nq]) = v;
            }
        } else {
#pragma unroll
            for (int l = tid; l < BN * BK / 4; l += THREADS) {
                int nn = l / (BK / 4);
                int kq = (l % (BK / 4)) * 4;
                float4 v = make_float4(0.f, 0.f, 0.f, 0.f);
                if (n0 + nn < Nn)
                    v = *reinterpret_cast<const float4*>(&B[(size_t)(n0 + nn) * Kn + k0 + kq]);
                Bs[kq + 0][nn] = v.x; Bs[kq + 1][nn] = v.y;
                Bs[kq + 2][nn] = v.z; Bs[kq + 3][nn] = v.w;
            }
        }
        __syncthreads();
#pragma unroll
        for (int k = 0; k < BK; k++) {
            float a[TM], b[TN];
#pragma unroll
            for (int i = 0; i < TM; i++) a[i] = As[k][ty * TM + i];
#pragma unroll
            for (int j = 0; j < TN; j++) b[j] = Bs[k][tx * TN + j];
#pragma unroll
            for (int i = 0; i < TM; i++)
#pragma unroll
                for (int j = 0; j < TN; j++) acc[i][j] += a[i] * b[j];
        }
        __syncthreads();
    }
#pragma unroll
    for (int i = 0; i < TM; i++) {
        int m = m0 + ty * TM + i;
        if (m >= Mn) continue;
#pragma unroll
        for (int j = 0; j < TN; j += 4) {
            int n = n0 + tx * TN + j;
            if (n >= Nn) continue;
            float4 v = make_float4(acc[i][j], acc[i][j + 1], acc[i][j + 2], acc[i][j + 3]);
            if (BIAS) {
                v.x += bias[n]; v.y += bias[n + 1]; v.z += bias[n + 2]; v.w += bias[n + 3];
            }
            if (RELU) {
                v.x = fmaxf(v.x, 0.f); v.y = fmaxf(v.y, 0.f);
                v.z = fmaxf(v.z, 0.f); v.w = fmaxf(v.w, 0.f);
            }
            *reinterpret_cast<float4*>(&C[(size_t)m * Nn + n]) = v;
        }
    }
}

// ---------------- host-side orchestration -----------------------------------
static inline dim3 gemm_grid(int Mn, int Nn, int BM, int BN) {
    return dim3((Nn + BN - 1) / BN, (Mn + BM - 1) / BM);
}

extern "C" void kernel_launch(void* const* d_in, const int* in_sizes, int n_in,
                              void* d_out, int out_size) {
    const float* x_in[2]  = { (const float*)d_in[0], (const float*)d_in[1] };
    const float* dmat[2]  = { (const float*)d_in[2], (const float*)d_in[3] };
    const int*   ei[2]    = { (const int*)d_in[4],   (const int*)d_in[5]   };
    const float* W1[2]    = { (const float*)d_in[6],  (const float*)d_in[10] };
    const float* b1[2]    = { (const float*)d_in[7],  (const float*)d_in[11] };
    const float* W2[2]    = { (const float*)d_in[8],  (const float*)d_in[12] };
    const float* b2[2]    = { (const float*)d_in[9],  (const float*)d_in[13] };
    const float* L1w[2]   = { (const float*)d_in[14], (const float*)d_in[20] };
    const float* L1b[2]   = { (const float*)d_in[15], (const float*)d_in[21] };
    const float* L2w[2]   = { (const float*)d_in[16], (const float*)d_in[22] };
    const float* L2b[2]   = { (const float*)d_in[17], (const float*)d_in[23] };
    const float* L3w[2]   = { (const float*)d_in[18], (const float*)d_in[24] };
    const float* L3b[2]   = { (const float*)d_in[19], (const float*)d_in[25] };
    float* out = (float*)d_out;

    float *p_t, *p_h, *p_m1, *p_m2, *p_m3;
    cudaGetSymbolAddress((void**)&p_t,  g_t);
    cudaGetSymbolAddress((void**)&p_h,  g_h);
    cudaGetSymbolAddress((void**)&p_m1, g_m1);
    cudaGetSymbolAddress((void**)&p_m2, g_m2);
    cudaGetSymbolAddress((void**)&p_m3, g_m3);

    const int TB = 256;
    const int gN = (N_NODES + TB - 1) / TB;
    const int gE = (N_EDGES + TB - 1) / TB;

    for (int g = 0; g < 2; g++) {
        float* t  = p_t  + (size_t)g * N_NODES * F0;
        float* h  = p_h  + (size_t)g * N_NODES * F0;
        float* m1 = p_m1 + (size_t)g * N_NODES * 256;
        float* m2 = p_m2 + (size_t)g * N_NODES * 128;
        float* m3 = p_m3 + (size_t)g * N_NODES * 64;

        init_kernel<<<gN, TB>>>(g);
        edge_kernel<<<gE, TB>>>(dmat[g], ei[g], g);
        dinv_kernel<<<gN, TB>>>(g);
        coeff_kernel<<<gE, TB>>>(ei[g], g);
        scan_kernel<<<1, 1024>>>(g);
        scatter_kernel<<<gE, TB>>>(ei[g], g);

        // GCN layer 1: t = x @ W1 ; h = relu(aggregate(t) + b1)
        gemm_kernel<128, 128, 16, 8, 8, false, false, false>
            <<<gemm_grid(N_NODES, F0, 128, 128), 256>>>(x_in[g], W1[g], nullptr, t,
                                                        N_NODES, F0, F0);
        aggregate_kernel<<<N_NODES, 128>>>(t, b1[g], h, g);

        // GCN layer 2: t = h @ W2 ; h = relu(aggregate(t) + b2)
        gemm_kernel<128, 128, 16, 8, 8, false, false, false>
            <<<gemm_grid(N_NODES, F0, 128, 128), 256>>>(h, W2[g], nullptr, t,
                                                        N_NODES, F0, F0);
        aggregate_kernel<<<N_NODES, 128>>>(t, b2[g], h, g);

        // MLP: 512 -> 256 -> 128 -> 64, relu each
        gemm_kernel<64, 64, 16, 4, 4, false, true, true>
            <<<gemm_grid(N_NODES, 256, 64, 64), 256>>>(h, L1w[g], L1b[g], m1,
                                                       N_NODES, 256, F0);
        gemm_kernel<64, 64, 16, 4, 4, false, true, true>
            <<<gemm_grid(N_NODES, 128, 64, 64), 256>>>(m1, L2w[g], L2b[g], m2,
                                                       N_NODES, 128, 256);
        gemm_kernel<64, 64, 16, 4, 4, false, true, true>
            <<<gemm_grid(N_NODES, 64, 64, 64), 256>>>(m2, L3w[g], L3b[g], m3,
                                                      N_NODES, 64, 128);
    }

    // final: out = x64_m @ y64_d^T   [8000 x 8000]
    gemm_kernel<128, 128, 16, 8, 8, true, false, false>
        <<<gemm_grid(N_NODES, N_NODES, 128, 128), 256>>>(
            p_m3, p_m3 + (size_t)N_NODES * 64, nullptr, out,
            N_NODES, N_NODES, 64);
}

// round 3
// speedup vs baseline: 1.6989x; 1.6989x over previous
#include <cuda_runtime.h>
#include <math.h>

#define N_NODES 8000
#define N_EDGES 256000
#define F0      512

// ---------------- scratch (static device allocations; no cudaMalloc) --------
__device__ float g_w    [2][N_EDGES];
__device__ float g_dinv [2][N_NODES];
__device__ float g_coeff[2][N_EDGES];
__device__ int   g_hist [2][N_NODES];
__device__ int   g_offs [2][N_NODES + 1];
__device__ int   g_fill [2][N_NODES];
__device__ int   g_crow [2][N_EDGES];
__device__ float g_ccoef[2][N_EDGES];
__device__ float g_t    [2][N_NODES * F0];
__device__ float g_h    [2][N_NODES * F0];
__device__ float g_m1   [2][N_NODES * 256];
__device__ float g_m2   [2][N_NODES * 128];
__device__ float g_m3   [2][N_NODES * 64];

// ---------------- edge / degree prep ----------------------------------------
__global__ void init_kernel(int g) {
    int i = blockIdx.x * blockDim.x + threadIdx.x;
    if (i < N_NODES) { g_dinv[g][i] = 1.0f; g_hist[g][i] = 0; }
}

__global__ void edge_kernel(const float* __restrict__ data,
                            const int* __restrict__ ei, int g) {
    int e = blockIdx.x * blockDim.x + threadIdx.x;
    if (e < N_EDGES) {
        int r = ei[e];
        int c = ei[N_EDGES + e];
        float v = fmaxf(data[(size_t)r * N_NODES + c], 0.0f);
        g_w[g][e] = v;
        atomicAdd(&g_dinv[g][c], v);
        atomicAdd(&g_hist[g][c], 1);
    }
}

__global__ void dinv_kernel(int g) {
    int i = blockIdx.x * blockDim.x + threadIdx.x;
    if (i < N_NODES) g_dinv[g][i] = rsqrtf(g_dinv[g][i]);
}

__global__ void coeff_kernel(const int* __restrict__ ei, int g) {
    int e = blockIdx.x * blockDim.x + threadIdx.x;
    if (e < N_EDGES) {
        int r = ei[e];
        int c = ei[N_EDGES + e];
        g_coeff[g][e] = g_dinv[g][r] * g_w[g][e] * g_dinv[g][c];
    }
}

__global__ void scan_kernel(int g) {
    __shared__ int s[1024];
    int t = threadIdx.x;
    int base = t * 8;
    int loc[8];
    int sum = 0;
#pragma unroll
    for (int j = 0; j < 8; j++) {
        int i = base + j;
        int v = (i < N_NODES) ? g_hist[g][i] : 0;
        loc[j] = sum;
        sum += v;
    }
    s[t] = sum;
    __syncthreads();
    for (int d = 1; d < 1024; d <<= 1) {
        int v = (t >= d) ? s[t - d] : 0;
        __syncthreads();
        s[t] += v;
        __syncthreads();
    }
    int cbase = s[t] - sum;
#pragma unroll
    for (int j = 0; j < 8; j++) {
        int i = base + j;
        if (i < N_NODES) {
            int o = cbase + loc[j];
            g_offs[g][i] = o;
            g_fill[g][i] = o;
        }
    }
    if (t == 0) g_offs[g][N_NODES] = N_EDGES;
}

__global__ void scatter_kernel(const int* __restrict__ ei, int g) {
    int e = blockIdx.x * blockDim.x + threadIdx.x;
    if (e < N_EDGES) {
        int c = ei[N_EDGES + e];
        int p = atomicAdd(&g_fill[g][c], 1);
        g_crow[g][p]  = ei[e];
        g_ccoef[g][p] = g_coeff[g][e];
    }
}

// ---------------- GCN aggregation -------------------------------------------
__global__ void aggregate_kernel(const float* __restrict__ t,
                                 const float* __restrict__ bias,
                                 float* __restrict__ out, int g) {
    int c = blockIdx.x;
    int f = threadIdx.x * 4;
    float dv = g_dinv[g][c];
    float sc = dv * dv;
    float4 v = *reinterpret_cast<const float4*>(&t[(size_t)c * F0 + f]);
    float4 acc = make_float4(v.x * sc, v.y * sc, v.z * sc, v.w * sc);
    int e0 = g_offs[g][c], e1 = g_offs[g][c + 1];
#pragma unroll 4
    for (int e = e0; e < e1; e++) {
        int   r  = g_crow[g][e];
        float cf = g_ccoef[g][e];
        float4 u = *reinterpret_cast<const float4*>(&t[(size_t)r * F0 + f]);
        acc.x += cf * u.x; acc.y += cf * u.y; acc.z += cf * u.z; acc.w += cf * u.w;
    }
    float4 b = *reinterpret_cast<const float4*>(&bias[f]);
    acc.x = fmaxf(acc.x + b.x, 0.0f);
    acc.y = fmaxf(acc.y + b.y, 0.0f);
    acc.z = fmaxf(acc.z + b.z, 0.0f);
    acc.w = fmaxf(acc.w + b.w, 0.0f);
    *reinterpret_cast<float4*>(&out[(size_t)c * F0 + f]) = acc;
}

// ---------------- TF32 tensor-core GEMM --------------------------------------
// C[Mn,Nn] = A[Mn,Kn] @ B  (B is [Kn,Nn] if !TRANSB else [Nn,Kn])
// BM=128, BN=64, BK=16, 128 threads (4 warps, 2x2 warp grid, 64x32 warp tile)
// Requires Kn % 16 == 0, Nn % 64 == 0.
__device__ __forceinline__ unsigned f2tf(float x) {
    unsigned u;
    asm("cvt.rna.tf32.f32 %0, %1;" : "=r"(u) : "f"(x));
    return u;
}

template <bool TRANSB, bool BIAS, bool RELU>
__global__ __launch_bounds__(128)
void tf32_gemm(const float* __restrict__ A, const float* __restrict__ B,
               const float* __restrict__ bias, float* __restrict__ C,
               int Mn, int Nn, int Kn) {
    constexpr int BM = 128, BN = 64, BK = 16, LDS = BK + 4;  // stride 20: conflict-free
    __shared__ unsigned As[BM * LDS];
    __shared__ unsigned Bs[BN * LDS];

    const int tid  = threadIdx.x;
    const int lane = tid & 31;
    const int wid  = tid >> 5;
    const int wm   = (wid & 1) * 64;   // warp m offset within block
    const int wn   = (wid >> 1) * 32;  // warp n offset within block
    const int q    = lane >> 2;        // 0..7
    const int r    = lane & 3;         // 0..3
    const int m0   = blockIdx.y * BM;
    const int n0   = blockIdx.x * BN;

    float c[4][4][4];
#pragma unroll
    for (int i = 0; i < 4; i++)
#pragma unroll
        for (int j = 0; j < 4; j++)
#pragma unroll
            for (int k = 0; k < 4; k++) c[i][j][k] = 0.0f;

    for (int k0 = 0; k0 < Kn; k0 += BK) {
        // load A tile: As[m][k], rows guarded
#pragma unroll
        for (int l = tid; l < BM * (BK / 4); l += 128) {
            int row = l >> 2;
            int kq  = (l & 3) * 4;
            float4 v = make_float4(0.f, 0.f, 0.f, 0.f);
            if (m0 + row < Mn)
                v = *reinterpret_cast<const float4*>(&A[(size_t)(m0 + row) * Kn + k0 + kq]);
            As[row * LDS + kq + 0] = f2tf(v.x);
            As[row * LDS + kq + 1] = f2tf(v.y);
            As[row * LDS + kq + 2] = f2tf(v.z);
            As[row * LDS + kq + 3] = f2tf(v.w);
        }
        // load B tile transposed into Bs[n][k]
        if (!TRANSB) {
#pragma unroll
            for (int l = tid; l < BK * BN; l += 128) {
                int k = l >> 6;       // l / BN
                int n = l & 63;       // l % BN
                Bs[n * LDS + k] = f2tf(B[(size_t)(k0 + k) * Nn + n0 + n]);
            }
        } else {
#pragma unroll
            for (int l = tid; l < BN * (BK / 4); l += 128) {
                int n  = l >> 2;
                int kq = (l & 3) * 4;
                float4 v = *reinterpret_cast<const float4*>(&B[(size_t)(n0 + n) * Kn + k0 + kq]);
                Bs[n * LDS + kq + 0] = f2tf(v.x);
                Bs[n * LDS + kq + 1] = f2tf(v.y);
                Bs[n * LDS + kq + 2] = f2tf(v.z);
                Bs[n * LDS + kq + 3] = f2tf(v.w);
            }
        }
        __syncthreads();

#pragma unroll
        for (int kk = 0; kk < BK; kk += 8) {
            unsigned a[4][4], b[4][2];
#pragma unroll
            for (int tm = 0; tm < 4; tm++) {
                int row = wm + tm * 16 + q;
                a[tm][0] = As[(row)     * LDS + kk + r];
                a[tm][1] = As[(row + 8) * LDS + kk + r];
                a[tm][2] = As[(row)     * LDS + kk + 4 + r];
                a[tm][3] = As[(row + 8) * LDS + kk + 4 + r];
            }
#pragma unroll
            for (int tn = 0; tn < 4; tn++) {
                int col = wn + tn * 8 + q;
                b[tn][0] = Bs[col * LDS + kk + r];
                b[tn][1] = Bs[col * LDS + kk + 4 + r];
            }
#pragma unroll
            for (int tm = 0; tm < 4; tm++)
#pragma unroll
                for (int tn = 0; tn < 4; tn++) {
                    asm volatile(
                        "mma.sync.aligned.m16n8k8.row.col.f32.tf32.tf32.f32 "
                        "{%0,%1,%2,%3}, {%4,%5,%6,%7}, {%8,%9}, {%0,%1,%2,%3};"
                        : "+f"(c[tm][tn][0]), "+f"(c[tm][tn][1]),
                          "+f"(c[tm][tn][2]), "+f"(c[tm][tn][3])
                        : "r"(a[tm][0]), "r"(a[tm][1]), "r"(a[tm][2]), "r"(a[tm][3]),
                          "r"(b[tn][0]), "r"(b[tn][1]));
                }
        }
        __syncthreads();
    }

    // epilogue
#pragma unroll
    for (int tm = 0; tm < 4; tm++) {
        int row = m0 + wm + tm * 16 + q;
#pragma unroll
        for (int tn = 0; tn < 4; tn++) {
            int col = n0 + wn + tn * 8 + 2 * r;
            float v0 = c[tm][tn][0], v1 = c[tm][tn][1];
            float v2 = c[tm][tn][2], v3 = c[tm][tn][3];
            if (BIAS) {
                float bb0 = bias[col], bb1 = bias[col + 1];
                v0 += bb0; v1 += bb1; v2 += bb0; v3 += bb1;
            }
            if (RELU) {
                v0 = fmaxf(v0, 0.f); v1 = fmaxf(v1, 0.f);
                v2 = fmaxf(v2, 0.f); v3 = fmaxf(v3, 0.f);
            }
            if (row < Mn)
                *reinterpret_cast<float2*>(&C[(size_t)row * Nn + col]) = make_float2(v0, v1);
            if (row + 8 < Mn)
                *reinterpret_cast<float2*>(&C[(size_t)(row + 8) * Nn + col]) = make_float2(v2, v3);
        }
    }
}

// ---------------- fp32 fallback GEMM (small MLP layers) ----------------------
template <int BM, int BN, int BK, int TM, int TN, bool BIAS, bool RELU>
__global__ __launch_bounds__((BM / TM) * (BN / TN))
void gemm_kernel(const float* __restrict__ A, const float* __restrict__ B,
                 const float* __restrict__ bias, float* __restrict__ C,
                 int Mn, int Nn, int Kn) {
    constexpr int THREADS = (BM / TM) * (BN / TN);
    __shared__ float As[BK][BM];
    __shared__ float Bs[BK][BN];
    const int tid = threadIdx.x;
    const int tx = tid % (BN / TN);
    const int ty = tid / (BN / TN);
    const int m0 = blockIdx.y * BM;
    const int n0 = blockIdx.x * BN;

    float acc[TM][TN];
#pragma unroll
    for (int i = 0; i < TM; i++)
#pragma unroll
        for (int j = 0; j < TN; j++) acc[i][j] = 0.0f;

    for (int k0 = 0; k0 < Kn; k0 += BK) {
#pragma unroll
        for (int l = tid; l < BM * BK / 4; l += THREADS) {
            int row = l / (BK / 4);
            int kq  = (l % (BK / 4)) * 4;
            float4 v = make_float4(0.f, 0.f, 0.f, 0.f);
            if (m0 + row < Mn)
                v = *reinterpret_cast<const float4*>(&A[(size_t)(m0 + row) * Kn + k0 + kq]);
            As[kq + 0][row] = v.x; As[kq + 1][row] = v.y;
            As[kq + 2][row] = v.z; As[kq + 3][row] = v.w;
        }
#pragma unroll
        for (int l = tid; l < BK * BN / 4; l += THREADS) {
            int kk = l / (BN / 4);
            int nq = (l % (BN / 4)) * 4;
            float4 v = make_float4(0.f, 0.f, 0.f, 0.f);
            if (n0 + nq < Nn)
                v = *reinterpret_cast<const float4*>(&B[(size_t)(k0 + kk) * Nn + n0 + nq]);
            *reinterpret_cast<float4*>(&Bs[kk][nq]) = v;
        }
        __syncthreads();
#pragma unroll
        for (int k = 0; k < BK; k++) {
            float a[TM], b[TN];
#pragma unroll
            for (int i = 0; i < TM; i++) a[i] = As[k][ty * TM + i];
#pragma unroll
            for (int j = 0; j < TN; j++) b[j] = Bs[k][tx * TN + j];
#pragma unroll
            for (int i = 0; i < TM; i++)
#pragma unroll
                for (int j = 0; j < TN; j++) acc[i][j] += a[i] * b[j];
        }
        __syncthreads();
    }
#pragma unroll
    for (int i = 0; i < TM; i++) {
        int m = m0 + ty * TM + i;
        if (m >= Mn) continue;
#pragma unroll
        for (int j = 0; j < TN; j += 4) {
            int n = n0 + tx * TN + j;
            if (n >= Nn) continue;
            float4 v = make_float4(acc[i][j], acc[i][j + 1], acc[i][j + 2], acc[i][j + 3]);
            if (BIAS) {
                v.x += bias[n]; v.y += bias[n + 1]; v.z += bias[n + 2]; v.w += bias[n + 3];
            }
            if (RELU) {
                v.x = fmaxf(v.x, 0.f); v.y = fmaxf(v.y, 0.f);
                v.z = fmaxf(v.z, 0.f); v.w = fmaxf(v.w, 0.f);
            }
            *reinterpret_cast<float4*>(&C[(size_t)m * Nn + n]) = v;
        }
    }
}

// ---------------- host-side orchestration -----------------------------------
extern "C" void kernel_launch(void* const* d_in, const int* in_sizes, int n_in,
                              void* d_out, int out_size) {
    const float* x_in[2]  = { (const float*)d_in[0], (const float*)d_in[1] };
    const float* dmat[2]  = { (const float*)d_in[2], (const float*)d_in[3] };
    const int*   ei[2]    = { (const int*)d_in[4],   (const int*)d_in[5]   };
    const float* W1[2]    = { (const float*)d_in[6],  (const float*)d_in[10] };
    const float* b1[2]    = { (const float*)d_in[7],  (const float*)d_in[11] };
    const float* W2[2]    = { (const float*)d_in[8],  (const float*)d_in[12] };
    const float* b2[2]    = { (const float*)d_in[9],  (const float*)d_in[13] };
    const float* L1w[2]   = { (const float*)d_in[14], (const float*)d_in[20] };
    const float* L1b[2]   = { (const float*)d_in[15], (const float*)d_in[21] };
    const float* L2w[2]   = { (const float*)d_in[16], (const float*)d_in[22] };
    const float* L2b[2]   = { (const float*)d_in[17], (const float*)d_in[23] };
    const float* L3w[2]   = { (const float*)d_in[18], (const float*)d_in[24] };
    const float* L3b[2]   = { (const float*)d_in[19], (const float*)d_in[25] };
    float* out = (float*)d_out;

    float *p_t, *p_h, *p_m1, *p_m2, *p_m3;
    cudaGetSymbolAddress((void**)&p_t,  g_t);
    cudaGetSymbolAddress((void**)&p_h,  g_h);
    cudaGetSymbolAddress((void**)&p_m1, g_m1);
    cudaGetSymbolAddress((void**)&p_m2, g_m2);
    cudaGetSymbolAddress((void**)&p_m3, g_m3);

    const int TB = 256;
    const int gN = (N_NODES + TB - 1) / TB;
    const int gE = (N_EDGES + TB - 1) / TB;
    const int MB = (N_NODES + 127) / 128;   // 63 row-blocks

    for (int g = 0; g < 2; g++) {
        float* t  = p_t  + (size_t)g * N_NODES * F0;
        float* h  = p_h  + (size_t)g * N_NODES * F0;
        float* m1 = p_m1 + (size_t)g * N_NODES * 256;
        float* m2 = p_m2 + (size_t)g * N_NODES * 128;
        float* m3 = p_m3 + (size_t)g * N_NODES * 64;

        init_kernel<<<gN, TB>>>(g);
        edge_kernel<<<gE, TB>>>(dmat[g], ei[g], g);
        dinv_kernel<<<gN, TB>>>(g);
        coeff_kernel<<<gE, TB>>>(ei[g], g);
        scan_kernel<<<1, 1024>>>(g);
        scatter_kernel<<<gE, TB>>>(ei[g], g);

        // GCN layer 1 (tf32): t = x @ W1 ; h = relu(aggregate(t) + b1)
        tf32_gemm<false, false, false><<<dim3(F0 / 64, MB), 128>>>(
            x_in[g], W1[g], nullptr, t, N_NODES, F0, F0);
        aggregate_kernel<<<N_NODES, 128>>>(t, b1[g], h, g);

        // GCN layer 2 (tf32)
        tf32_gemm<false, false, false><<<dim3(F0 / 64, MB), 128>>>(
            h, W2[g], nullptr, t, N_NODES, F0, F0);
        aggregate_kernel<<<N_NODES, 128>>>(t, b2[g], h, g);

        // MLP: L1 tf32, L2/L3 fp32
        tf32_gemm<false, true, true><<<dim3(256 / 64, MB), 128>>>(
            h, L1w[g], L1b[g], m1, N_NODES, 256, F0);
        gemm_kernel<64, 64, 16, 4, 4, true, true>
            <<<dim3(2, (N_NODES + 63) / 64), 256>>>(m1, L2w[g], L2b[g], m2,
                                                    N_NODES, 128, 256);
        gemm_kernel<64, 64, 16, 4, 4, true, true>
            <<<dim3(1, (N_NODES + 63) / 64), 256>>>(m2, L3w[g], L3b[g], m3,
                                                    N_NODES, 64, 128);
    }

    // final (tf32, TRANSB): out = x64_m @ y64_d^T
    tf32_gemm<true, false, false><<<dim3(N_NODES / 64, MB), 128>>>(
        p_m3, p_m3 + (size_t)N_NODES * 64, nullptr, out,
        N_NODES, N_NODES, 64);
}

// round 4
// speedup vs baseline: 1.9966x; 1.1752x over previous
#include <cuda_runtime.h>
#include <math.h>

#define N_NODES 8000
#define N_EDGES 256000
#define F0      512

// ---------------- scratch (static device allocations; no cudaMalloc) --------
__device__ float g_w    [2][N_EDGES];
__device__ float g_dinv [2][N_NODES];
__device__ float g_coeff[2][N_EDGES];
__device__ int   g_hist [2][N_NODES];
__device__ int   g_offs [2][N_NODES + 1];
__device__ int   g_fill [2][N_NODES];
__device__ int   g_crow [2][N_EDGES];
__device__ float g_ccoef[2][N_EDGES];
__device__ float g_t    [2][N_NODES * F0];
__device__ float g_h    [2][N_NODES * F0];
__device__ float g_m1   [2][N_NODES * 256];
__device__ float g_m2   [2][N_NODES * 128];
__device__ float g_m3   [2][N_NODES * 64];

// ---------------- edge / degree prep (both graphs batched: blockIdx.y = g) --
__global__ void init_kernel() {
    int i = blockIdx.x * blockDim.x + threadIdx.x;
    int g = blockIdx.y;
    if (i < N_NODES) { g_dinv[g][i] = 1.0f; g_hist[g][i] = 0; }
}

__global__ void edge_kernel(const float* __restrict__ d0, const float* __restrict__ d1,
                            const int* __restrict__ e0, const int* __restrict__ e1) {
    int e = blockIdx.x * blockDim.x + threadIdx.x;
    int g = blockIdx.y;
    const float* data = g ? d1 : d0;
    const int*   ei   = g ? e1 : e0;
    if (e < N_EDGES) {
        int r = ei[e];
        int c = ei[N_EDGES + e];
        float v = fmaxf(data[(size_t)r * N_NODES + c], 0.0f);
        g_w[g][e] = v;
        atomicAdd(&g_dinv[g][c], v);
        atomicAdd(&g_hist[g][c], 1);
    }
}

__global__ void dinv_kernel() {
    int i = blockIdx.x * blockDim.x + threadIdx.x;
    int g = blockIdx.y;
    if (i < N_NODES) g_dinv[g][i] = rsqrtf(g_dinv[g][i]);
}

__global__ void coeff_kernel(const int* __restrict__ e0, const int* __restrict__ e1) {
    int e = blockIdx.x * blockDim.x + threadIdx.x;
    int g = blockIdx.y;
    const int* ei = g ? e1 : e0;
    if (e < N_EDGES) {
        int r = ei[e];
        int c = ei[N_EDGES + e];
        g_coeff[g][e] = g_dinv[g][r] * g_w[g][e] * g_dinv[g][c];
    }
}

// per-graph exclusive scan (one block per graph)
__global__ void scan_kernel() {
    __shared__ int s[1024];
    int g = blockIdx.x;
    int t = threadIdx.x;
    int base = t * 8;
    int loc[8];
    int sum = 0;
#pragma unroll
    for (int j = 0; j < 8; j++) {
        int i = base + j;
        int v = (i < N_NODES) ? g_hist[g][i] : 0;
        loc[j] = sum;
        sum += v;
    }
    s[t] = sum;
    __syncthreads();
    for (int d = 1; d < 1024; d <<= 1) {
        int v = (t >= d) ? s[t - d] : 0;
        __syncthreads();
        s[t] += v;
        __syncthreads();
    }
    int cbase = s[t] - sum;
#pragma unroll
    for (int j = 0; j < 8; j++) {
        int i = base + j;
        if (i < N_NODES) {
            int o = cbase + loc[j];
            g_offs[g][i] = o;
            g_fill[g][i] = o;
        }
    }
    if (t == 0) g_offs[g][N_NODES] = N_EDGES;
}

__global__ void scatter_kernel(const int* __restrict__ e0, const int* __restrict__ e1) {
    int e = blockIdx.x * blockDim.x + threadIdx.x;
    int g = blockIdx.y;
    const int* ei = g ? e1 : e0;
    if (e < N_EDGES) {
        int c = ei[N_EDGES + e];
        int p = atomicAdd(&g_fill[g][c], 1);
        g_crow[g][p]  = ei[e];
        g_ccoef[g][p] = g_coeff[g][e];
    }
}

// ---------------- GCN aggregation (blockIdx.y = g) ---------------------------
__global__ void aggregate_kernel(const float* __restrict__ t0, const float* __restrict__ t1,
                                 const float* __restrict__ bias0, const float* __restrict__ bias1,
                                 float* __restrict__ o0, float* __restrict__ o1) {
    int c = blockIdx.x;
    int g = blockIdx.y;
    const float* t    = g ? t1 : t0;
    const float* bias = g ? bias1 : bias0;
    float* out        = g ? o1 : o0;
    int f = threadIdx.x * 4;
    float dv = g_dinv[g][c];
    float sc = dv * dv;
    float4 v = *reinterpret_cast<const float4*>(&t[(size_t)c * F0 + f]);
    float4 acc = make_float4(v.x * sc, v.y * sc, v.z * sc, v.w * sc);
    int e0 = g_offs[g][c], e1 = g_offs[g][c + 1];
#pragma unroll 4
    for (int e = e0; e < e1; e++) {
        int   r  = g_crow[g][e];
        float cf = g_ccoef[g][e];
        float4 u = *reinterpret_cast<const float4*>(&t[(size_t)r * F0 + f]);
        acc.x += cf * u.x; acc.y += cf * u.y; acc.z += cf * u.z; acc.w += cf * u.w;
    }
    float4 b = *reinterpret_cast<const float4*>(&bias[f]);
    acc.x = fmaxf(acc.x + b.x, 0.0f);
    acc.y = fmaxf(acc.y + b.y, 0.0f);
    acc.z = fmaxf(acc.z + b.z, 0.0f);
    acc.w = fmaxf(acc.w + b.w, 0.0f);
    *reinterpret_cast<float4*>(&out[(size_t)c * F0 + f]) = acc;
}

// ---------------- TF32 tensor-core GEMM (128x128x16, 256 thr, reg prefetch) --
// C[Mn,Nn] = A[Mn,Kn] @ B  (B is [Kn,Nn] if !TRANSB else [Nn,Kn])
// Kn % 16 == 0, Nn % 4 == 0.  blockIdx.z selects graph (pointer pair).
__device__ __forceinline__ unsigned f2tf(float x) {
    unsigned u;
    asm("cvt.rna.tf32.f32 %0, %1;" : "=r"(u) : "f"(x));
    return u;
}

template <bool TRANSB, bool BIAS, bool RELU>
__global__ __launch_bounds__(256)
void tf32_gemm(const float* __restrict__ A0, const float* __restrict__ A1,
               const float* __restrict__ B0, const float* __restrict__ B1,
               const float* __restrict__ bias0, const float* __restrict__ bias1,
               float* __restrict__ C0, float* __restrict__ C1,
               int Mn, int Nn, int Kn) {
    constexpr int BM = 128, BN = 128, BK = 16;
    constexpr int LDA = BK + 4;      // As[m][k], stride 20: frag loads conflict-free
    constexpr int LDB = BN + 4;      // Bs[k][n], stride 132: frag loads conflict-free
    __shared__ unsigned As[BM * LDA];
    __shared__ unsigned Bs[BK * LDB];

    const int gsel = blockIdx.z;
    const float* A    = gsel ? A1 : A0;
    const float* B    = gsel ? B1 : B0;
    const float* bias = gsel ? bias1 : bias0;
    float*       C    = gsel ? C1 : C0;

    const int tid  = threadIdx.x;
    const int lane = tid & 31;
    const int wid  = tid >> 5;
    const int wm   = (wid & 1) * 64;
    const int wn   = (wid >> 1) * 32;
    const int q    = lane >> 2;
    const int r    = lane & 3;
    const int m0   = blockIdx.y * BM;
    const int n0   = blockIdx.x * BN;

    float c[4][4][4];
#pragma unroll
    for (int i = 0; i < 4; i++)
#pragma unroll
        for (int j = 0; j < 4; j++)
#pragma unroll
            for (int k = 0; k < 4; k++) c[i][j][k] = 0.0f;

    float4 ra[2], rb[2];

    // ---- tile load (global -> regs) ----
    auto loadA = [&](int k0) {
#pragma unroll
        for (int i = 0; i < 2; i++) {
            int l = tid + i * 256;           // l < 512
            int row = l >> 2;
            int kq  = (l & 3) * 4;
            float4 v = make_float4(0.f, 0.f, 0.f, 0.f);
            if (m0 + row < Mn)
                v = *reinterpret_cast<const float4*>(&A[(size_t)(m0 + row) * Kn + k0 + kq]);
            ra[i] = v;
        }
    };
    auto loadB = [&](int k0) {
#pragma unroll
        for (int i = 0; i < 2; i++) {
            int l = tid + i * 256;           // l < 512
            float4 v = make_float4(0.f, 0.f, 0.f, 0.f);
            if (!TRANSB) {
                int k  = l >> 5;             // 0..15
                int nq = (l & 31) * 4;       // 0..124
                if (n0 + nq < Nn)
                    v = *reinterpret_cast<const float4*>(&B[(size_t)(k0 + k) * Nn + n0 + nq]);
            } else {
                int n  = l >> 2;             // 0..127
                int kq = (l & 3) * 4;
                if (n0 + n < Nn)
                    v = *reinterpret_cast<const float4*>(&B[(size_t)(n0 + n) * Kn + k0 + kq]);
            }
            rb[i] = v;
        }
    };
    // ---- tile store (regs -> smem, tf32 convert) ----
    auto storeA = [&]() {
#pragma unroll
        for (int i = 0; i < 2; i++) {
            int l = tid + i * 256;
            int row = l >> 2;
            int kq  = (l & 3) * 4;
            As[row * LDA + kq + 0] = f2tf(ra[i].x);
            As[row * LDA + kq + 1] = f2tf(ra[i].y);
            As[row * LDA + kq + 2] = f2tf(ra[i].z);
            As[row * LDA + kq + 3] = f2tf(ra[i].w);
        }
    };
    auto storeB = [&]() {
#pragma unroll
        for (int i = 0; i < 2; i++) {
            int l = tid + i * 256;
            if (!TRANSB) {
                int k  = l >> 5;
                int nq = (l & 31) * 4;
                Bs[k * LDB + nq + 0] = f2tf(rb[i].x);
                Bs[k * LDB + nq + 1] = f2tf(rb[i].y);
                Bs[k * LDB + nq + 2] = f2tf(rb[i].z);
                Bs[k * LDB + nq + 3] = f2tf(rb[i].w);
            } else {
                int n  = l >> 2;
                int kq = (l & 3) * 4;
                Bs[(kq + 0) * LDB + n] = f2tf(rb[i].x);
                Bs[(kq + 1) * LDB + n] = f2tf(rb[i].y);
                Bs[(kq + 2) * LDB + n] = f2tf(rb[i].z);
                Bs[(kq + 3) * LDB + n] = f2tf(rb[i].w);
            }
        }
    };

    loadA(0);
    loadB(0);

    for (int k0 = 0; k0 < Kn; k0 += BK) {
        storeA();
        storeB();
        __syncthreads();
        if (k0 + BK < Kn) { loadA(k0 + BK); loadB(k0 + BK); }

#pragma unroll
        for (int kk = 0; kk < BK; kk += 8) {
            unsigned a[4][4], b[4][2];
#pragma unroll
            for (int tm = 0; tm < 4; tm++) {
                int row = wm + tm * 16 + q;
                a[tm][0] = As[(row)     * LDA + kk + r];
                a[tm][1] = As[(row + 8) * LDA + kk + r];
                a[tm][2] = As[(row)     * LDA + kk + 4 + r];
                a[tm][3] = As[(row + 8) * LDA + kk + 4 + r];
            }
#pragma unroll
            for (int tn = 0; tn < 4; tn++) {
                int col = wn + tn * 8 + q;
                b[tn][0] = Bs[(kk + r)     * LDB + col];
                b[tn][1] = Bs[(kk + 4 + r) * LDB + col];
            }
#pragma unroll
            for (int tm = 0; tm < 4; tm++)
#pragma unroll
                for (int tn = 0; tn < 4; tn++) {
                    asm volatile(
                        "mma.sync.aligned.m16n8k8.row.col.f32.tf32.tf32.f32 "
                        "{%0,%1,%2,%3}, {%4,%5,%6,%7}, {%8,%9}, {%0,%1,%2,%3};"
                        : "+f"(c[tm][tn][0]), "+f"(c[tm][tn][1]),
                          "+f"(c[tm][tn][2]), "+f"(c[tm][tn][3])
                        : "r"(a[tm][0]), "r"(a[tm][1]), "r"(a[tm][2]), "r"(a[tm][3]),
                          "r"(b[tn][0]), "r"(b[tn][1]));
                }
        }
        __syncthreads();
    }

    // epilogue
#pragma unroll
    for (int tm = 0; tm < 4; tm++) {
        int row = m0 + wm + tm * 16 + q;
#pragma unroll
        for (int tn = 0; tn < 4; tn++) {
            int col = n0 + wn + tn * 8 + 2 * r;
            if (col >= Nn) continue;
            float v0 = c[tm][tn][0], v1 = c[tm][tn][1];
            float v2 = c[tm][tn][2], v3 = c[tm][tn][3];
            if (BIAS) {
                float bb0 = bias[col], bb1 = bias[col + 1];
                v0 += bb0; v1 += bb1; v2 += bb0; v3 += bb1;
            }
            if (RELU) {
                v0 = fmaxf(v0, 0.f); v1 = fmaxf(v1, 0.f);
                v2 = fmaxf(v2, 0.f); v3 = fmaxf(v3, 0.f);
            }
            if (row < Mn)
                *reinterpret_cast<float2*>(&C[(size_t)row * Nn + col]) = make_float2(v0, v1);
            if (row + 8 < Mn)
                *reinterpret_cast<float2*>(&C[(size_t)(row + 8) * Nn + col]) = make_float2(v2, v3);
        }
    }
}

// ---------------- fp32 GEMM for narrow MLP layers (blockIdx.z = g) -----------
template <int BM, int BN, int BK, int TM, int TN, bool BIAS, bool RELU>
__global__ __launch_bounds__((BM / TM) * (BN / TN))
void gemm_kernel(const float* __restrict__ A0, const float* __restrict__ A1,
                 const float* __restrict__ B0, const float* __restrict__ B1,
                 const float* __restrict__ bias0, const float* __restrict__ bias1,
                 float* __restrict__ C0, float* __restrict__ C1,
                 int Mn, int Nn, int Kn) {
    constexpr int THREADS = (BM / TM) * (BN / TN);
    __shared__ float As[BK][BM];
    __shared__ float Bs[BK][BN];
    const int gsel = blockIdx.z;
    const float* A    = gsel ? A1 : A0;
    const float* B    = gsel ? B1 : B0;
    const float* bias = gsel ? bias1 : bias0;
    float*       C    = gsel ? C1 : C0;
    const int tid = threadIdx.x;
    const int tx = tid % (BN / TN);
    const int ty = tid / (BN / TN);
    const int m0 = blockIdx.y * BM;
    const int n0 = blockIdx.x * BN;

    float acc[TM][TN];
#pragma unroll
    for (int i = 0; i < TM; i++)
#pragma unroll
        for (int j = 0; j < TN; j++) acc[i][j] = 0.0f;

    for (int k0 = 0; k0 < Kn; k0 += BK) {
#pragma unroll
        for (int l = tid; l < BM * BK / 4; l += THREADS) {
            int row = l / (BK / 4);
            int kq  = (l % (BK / 4)) * 4;
            float4 v = make_float4(0.f, 0.f, 0.f, 0.f);
            if (m0 + row < Mn)
                v = *reinterpret_cast<const float4*>(&A[(size_t)(m0 + row) * Kn + k0 + kq]);
            As[kq + 0][row] = v.x; As[kq + 1][row] = v.y;
            As[kq + 2][row] = v.z; As[kq + 3][row] = v.w;
        }
#pragma unroll
        for (int l = tid; l < BK * BN / 4; l += THREADS) {
            int kk = l / (BN / 4);
            int nq = (l % (BN / 4)) * 4;
            float4 v = make_float4(0.f, 0.f, 0.f, 0.f);
            if (n0 + nq < Nn)
                v = *reinterpret_cast<const float4*>(&B[(size_t)(k0 + kk) * Nn + n0 + nq]);
            *reinterpret_cast<float4*>(&Bs[kk][nq]) = v;
        }
        __syncthreads();
#pragma unroll
        for (int k = 0; k < BK; k++) {
            float a[TM], b[TN];
#pragma unroll
            for (int i = 0; i < TM; i++) a[i] = As[k][ty * TM + i];
#pragma unroll
            for (int j = 0; j < TN; j++) b[j] = Bs[k][tx * TN + j];
#pragma unroll
            for (int i = 0; i < TM; i++)
#pragma unroll
                for (int j = 0; j < TN; j++) acc[i][j] += a[i] * b[j];
        }
        __syncthreads();
    }
#pragma unroll
    for (int i = 0; i < TM; i++) {
        int m = m0 + ty * TM + i;
        if (m >= Mn) continue;
#pragma unroll
        for (int j = 0; j < TN; j += 4) {
            int n = n0 + tx * TN + j;
            if (n >= Nn) continue;
            float4 v = make_float4(acc[i][j], acc[i][j + 1], acc[i][j + 2], acc[i][j + 3]);
            if (BIAS) {
                v.x += bias[n]; v.y += bias[n + 1]; v.z += bias[n + 2]; v.w += bias[n + 3];
            }
            if (RELU) {
                v.x = fmaxf(v.x, 0.f); v.y = fmaxf(v.y, 0.f);
                v.z = fmaxf(v.z, 0.f); v.w = fmaxf(v.w, 0.f);
            }
            *reinterpret_cast<float4*>(&C[(size_t)m * Nn + n]) = v;
        }
    }
}

// ---------------- host-side orchestration -----------------------------------
extern "C" void kernel_launch(void* const* d_in, const int* in_sizes, int n_in,
                              void* d_out, int out_size) {
    const float* x_in[2]  = { (const float*)d_in[0], (const float*)d_in[1] };
    const float* dmat[2]  = { (const float*)d_in[2], (const float*)d_in[3] };
    const int*   ei[2]    = { (const int*)d_in[4],   (const int*)d_in[5]   };
    const float* W1[2]    = { (const float*)d_in[6],  (const float*)d_in[10] };
    const float* b1[2]    = { (const float*)d_in[7],  (const float*)d_in[11] };
    const float* W2[2]    = { (const float*)d_in[8],  (const float*)d_in[12] };
    const float* b2[2]    = { (const float*)d_in[9],  (const float*)d_in[13] };
    const float* L1w[2]   = { (const float*)d_in[14], (const float*)d_in[20] };
    const float* L1b[2]   = { (const float*)d_in[15], (const float*)d_in[21] };
    const float* L2w[2]   = { (const float*)d_in[16], (const float*)d_in[22] };
    const float* L2b[2]   = { (const float*)d_in[17], (const float*)d_in[23] };
    const float* L3w[2]   = { (const float*)d_in[18], (const float*)d_in[24] };
    const float* L3b[2]   = { (const float*)d_in[19], (const float*)d_in[25] };
    float* out = (float*)d_out;

    float *p_t, *p_h, *p_m1, *p_m2, *p_m3;
    cudaGetSymbolAddress((void**)&p_t,  g_t);
    cudaGetSymbolAddress((void**)&p_h,  g_h);
    cudaGetSymbolAddress((void**)&p_m1, g_m1);
    cudaGetSymbolAddress((void**)&p_m2, g_m2);
    cudaGetSymbolAddress((void**)&p_m3, g_m3);

    float* t[2]  = { p_t,  p_t  + (size_t)N_NODES * F0 };
    float* h[2]  = { p_h,  p_h  + (size_t)N_NODES * F0 };
    float* m1[2] = { p_m1, p_m1 + (size_t)N_NODES * 256 };
    float* m2[2] = { p_m2, p_m2 + (size_t)N_NODES * 128 };
    float* m3[2] = { p_m3, p_m3 + (size_t)N_NODES * 64 };

    const int TB = 256;
    const dim3 gN((N_NODES + TB - 1) / TB, 2);
    const dim3 gE((N_EDGES + TB - 1) / TB, 2);
    const int MB = (N_NODES + 127) / 128;   // 63

    // prep (both graphs per launch)
    init_kernel<<<gN, TB>>>();
    edge_kernel<<<gE, TB>>>(dmat[0], dmat[1], ei[0], ei[1]);
    dinv_kernel<<<gN, TB>>>();
    coeff_kernel<<<gE, TB>>>(ei[0], ei[1]);
    scan_kernel<<<2, 1024>>>();
    scatter_kernel<<<gE, TB>>>(ei[0], ei[1]);

    // GCN layer 1: t = x @ W1 ; h = relu(agg(t) + b1)
    tf32_gemm<false, false, false><<<dim3(F0 / 128, MB, 2), 256>>>(
        x_in[0], x_in[1], W1[0], W1[1], nullptr, nullptr, t[0], t[1],
        N_NODES, F0, F0);
    aggregate_kernel<<<dim3(N_NODES, 2), 128>>>(t[0], t[1], b1[0], b1[1], h[0], h[1]);

    // GCN layer 2
    tf32_gemm<false, false, false><<<dim3(F0 / 128, MB, 2), 256>>>(
        h[0], h[1], W2[0], W2[1], nullptr, nullptr, t[0], t[1],
        N_NODES, F0, F0);
    aggregate_kernel<<<dim3(N_NODES, 2), 128>>>(t[0], t[1], b2[0], b2[1], h[0], h[1]);

    // MLP: L1 tf32 (512->256), L2/L3 fp32
    tf32_gemm<false, true, true><<<dim3(256 / 128, MB, 2), 256>>>(
        h[0], h[1], L1w[0], L1w[1], L1b[0], L1b[1], m1[0], m1[1],
        N_NODES, 256, F0);
    gemm_kernel<64, 64, 16, 4, 4, true, true>
        <<<dim3(2, (N_NODES + 63) / 64, 2), 256>>>(
            m1[0], m1[1], L2w[0], L2w[1], L2b[0], L2b[1], m2[0], m2[1],
            N_NODES, 128, 256);
    gemm_kernel<64, 64, 16, 4, 4, true, true>
        <<<dim3(1, (N_NODES + 63) / 64, 2), 256>>>(
            m2[0], m2[1], L3w[0], L3w[1], L3b[0], L3b[1], m3[0], m3[1],
            N_NODES, 64, 128);

    // final (tf32, TRANSB): out = x64_m @ y64_d^T  [8000 x 8000]
    tf32_gemm<true, false, false><<<dim3((N_NODES + 127) / 128, MB, 1), 256>>>(
        m3[0], m3[0], m3[1], m3[1], nullptr, nullptr, out, out,
        N_NODES, N_NODES, 64);
}

// round 6
// speedup vs baseline: 2.0458x; 1.0246x over previous
#include <cuda_runtime.h>
#include <cuda_bf16.h>
#include <math.h>

#define N_NODES 8000
#define N_EDGES 256000
#define F0      512

// ---------------- scratch (static device allocations; no cudaMalloc) --------
__device__ float g_w    [2][N_EDGES];
__device__ float g_dinv [2][N_NODES];
__device__ float g_coeff[2][N_EDGES];
__device__ int   g_hist [2][N_NODES];
__device__ int   g_offs [2][N_NODES + 1];
__device__ int   g_fill [2][N_NODES];
__device__ int   g_crow [2][N_EDGES];
__device__ float g_ccoef[2][N_EDGES];
__device__ float g_t    [2][N_NODES * F0];
__device__ __nv_bfloat16 g_tb[2][N_NODES * F0];   // bf16 copy of t for gather
__device__ float g_h    [2][N_NODES * F0];
__device__ float g_m1   [2][N_NODES * 256];
__device__ float g_m2   [2][N_NODES * 128];
__device__ float g_m3   [2][N_NODES * 64];

// ---------------- edge / degree prep (both graphs batched: blockIdx.y = g) --
__global__ void init_kernel() {
    int i = blockIdx.x * blockDim.x + threadIdx.x;
    int g = blockIdx.y;
    if (i < N_NODES) { g_dinv[g][i] = 1.0f; g_hist[g][i] = 0; }
}

__global__ void edge_kernel(const float* __restrict__ d0, const float* __restrict__ d1,
                            const int* __restrict__ e0, const int* __restrict__ e1) {
    int e = blockIdx.x * blockDim.x + threadIdx.x;
    int g = blockIdx.y;
    const float* data = g ? d1 : d0;
    const int*   ei   = g ? e1 : e0;
    if (e < N_EDGES) {
        int r = ei[e];
        int c = ei[N_EDGES + e];
        float v = fmaxf(data[(size_t)r * N_NODES + c], 0.0f);
        g_w[g][e] = v;
        atomicAdd(&g_dinv[g][c], v);
        atomicAdd(&g_hist[g][c], 1);
    }
}

__global__ void dinv_kernel() {
    int i = blockIdx.x * blockDim.x + threadIdx.x;
    int g = blockIdx.y;
    if (i < N_NODES) g_dinv[g][i] = rsqrtf(g_dinv[g][i]);
}

__global__ void coeff_kernel(const int* __restrict__ e0, const int* __restrict__ e1) {
    int e = blockIdx.x * blockDim.x + threadIdx.x;
    int g = blockIdx.y;
    const int* ei = g ? e1 : e0;
    if (e < N_EDGES) {
        int r = ei[e];
        int c = ei[N_EDGES + e];
        g_coeff[g][e] = g_dinv[g][r] * g_w[g][e] * g_dinv[g][c];
    }
}

__global__ void scan_kernel() {
    __shared__ int s[1024];
    int g = blockIdx.x;
    int t = threadIdx.x;
    int base = t * 8;
    int loc[8];
    int sum = 0;
#pragma unroll
    for (int j = 0; j < 8; j++) {
        int i = base + j;
        int v = (i < N_NODES) ? g_hist[g][i] : 0;
        loc[j] = sum;
        sum += v;
    }
    s[t] = sum;
    __syncthreads();
    for (int d = 1; d < 1024; d <<= 1) {
        int v = (t >= d) ? s[t - d] : 0;
        __syncthreads();
        s[t] += v;
        __syncthreads();
    }
    int cbase = s[t] - sum;
#pragma unroll
    for (int j = 0; j < 8; j++) {
        int i = base + j;
        if (i < N_NODES) {
            int o = cbase + loc[j];
            g_offs[g][i] = o;
            g_fill[g][i] = o;
        }
    }
    if (t == 0) g_offs[g][N_NODES] = N_EDGES;
}

__global__ void scatter_kernel(const int* __restrict__ e0, const int* __restrict__ e1) {
    int e = blockIdx.x * blockDim.x + threadIdx.x;
    int g = blockIdx.y;
    const int* ei = g ? e1 : e0;
    if (e < N_EDGES) {
        int c = ei[N_EDGES + e];
        int p = atomicAdd(&g_fill[g][c], 1);
        g_crow[g][p]  = ei[e];
        g_ccoef[g][p] = g_coeff[g][e];
    }
}

// ---------------- GCN aggregation (bf16 neighbor gather, fp32 self+accum) ----
__global__ void aggregate_kernel(const float* __restrict__ t0, const float* __restrict__ t1,
                                 const float* __restrict__ bias0, const float* __restrict__ bias1,
                                 float* __restrict__ o0, float* __restrict__ o1) {
    int c = blockIdx.x;
    int g = blockIdx.y;
    const float* t    = g ? t1 : t0;
    const float* bias = g ? bias1 : bias0;
    float* out        = g ? o1 : o0;
    const __nv_bfloat16* __restrict__ tb = g_tb[g];
    const int* __restrict__ crow = g_crow[g];
    const float* __restrict__ ccoef = g_ccoef[g];
    int f = threadIdx.x * 4;
    float dv = g_dinv[g][c];
    float sc = dv * dv;
    float4 v = *reinterpret_cast<const float4*>(&t[(size_t)c * F0 + f]);
    float4 acc = make_float4(v.x * sc, v.y * sc, v.z * sc, v.w * sc);
    int e0 = g_offs[g][c], e1 = g_offs[g][c + 1];
#pragma unroll 4
    for (int e = e0; e < e1; e++) {
        int   r  = crow[e];
        float cf = ccoef[e];
        uint2 raw = *reinterpret_cast<const uint2*>(&tb[(size_t)r * F0 + f]);
        float2 u0 = __bfloat1622float2(*reinterpret_cast<__nv_bfloat162*>(&raw.x));
        float2 u1 = __bfloat1622float2(*reinterpret_cast<__nv_bfloat162*>(&raw.y));
        acc.x += cf * u0.x; acc.y += cf * u0.y;
        acc.z += cf * u1.x; acc.w += cf * u1.y;
    }
    float4 b = *reinterpret_cast<const float4*>(&bias[f]);
    acc.x = fmaxf(acc.x + b.x, 0.0f);
    acc.y = fmaxf(acc.y + b.y, 0.0f);
    acc.z = fmaxf(acc.z + b.z, 0.0f);
    acc.w = fmaxf(acc.w + b.w, 0.0f);
    *reinterpret_cast<float4*>(&out[(size_t)c * F0 + f]) = acc;
}

// ---------------- TF32 tensor-core GEMM (128x128x16, 256 thr, reg prefetch) --
// C[Mn,Nn] = A[Mn,Kn] @ B  (B is [Kn,Nn] if !TRANSB else [Nn,Kn])
// WBF: additionally write bf16 copy of C into g_tb[blockIdx.z].
__device__ __forceinline__ unsigned f2tf(float x) {
    unsigned u;
    asm("cvt.rna.tf32.f32 %0, %1;" : "=r"(u) : "f"(x));
    return u;
}

template <bool TRANSB, bool BIAS, bool RELU, bool WBF>
__global__ __launch_bounds__(256)
void tf32_gemm(const float* __restrict__ A0, const float* __restrict__ A1,
               const float* __restrict__ B0, const float* __restrict__ B1,
               const float* __restrict__ bias0, const float* __restrict__ bias1,
               float* __restrict__ C0, float* __restrict__ C1,
               int Mn, int Nn, int Kn) {
    constexpr int BM = 128, BN = 128, BK = 16;
    constexpr int LDA = BK + 4;
    constexpr int LDB = BN + 4;
    __shared__ unsigned As[BM * LDA];
    __shared__ unsigned Bs[BK * LDB];

    const int gsel = blockIdx.z;
    const float* A    = gsel ? A1 : A0;
    const float* B    = gsel ? B1 : B0;
    const float* bias = gsel ? bias1 : bias0;
    float*       C    = gsel ? C1 : C0;
    __nv_bfloat16* CB = WBF ? g_tb[gsel] : nullptr;

    const int tid  = threadIdx.x;
    const int lane = tid & 31;
    const int wid  = tid >> 5;
    const int wm   = (wid & 1) * 64;
    const int wn   = (wid >> 1) * 32;
    const int q    = lane >> 2;
    const int r    = lane & 3;
    const int m0   = blockIdx.y * BM;
    const int n0   = blockIdx.x * BN;

    float c[4][4][4];
#pragma unroll
    for (int i = 0; i < 4; i++)
#pragma unroll
        for (int j = 0; j < 4; j++)
#pragma unroll
            for (int k = 0; k < 4; k++) c[i][j][k] = 0.0f;

    float4 ra[2], rb[2];

    auto loadA = [&](int k0) {
#pragma unroll
        for (int i = 0; i < 2; i++) {
            int l = tid + i * 256;
            int row = l >> 2;
            int kq  = (l & 3) * 4;
            float4 v = make_float4(0.f, 0.f, 0.f, 0.f);
            if (m0 + row < Mn)
                v = *reinterpret_cast<const float4*>(&A[(size_t)(m0 + row) * Kn + k0 + kq]);
            ra[i] = v;
        }
    };
    auto loadB = [&](int k0) {
#pragma unroll
        for (int i = 0; i < 2; i++) {
            int l = tid + i * 256;
            float4 v = make_float4(0.f, 0.f, 0.f, 0.f);
            if (!TRANSB) {
                int k  = l >> 5;
                int nq = (l & 31) * 4;
                if (n0 + nq < Nn)
                    v = *reinterpret_cast<const float4*>(&B[(size_t)(k0 + k) * Nn + n0 + nq]);
            } else {
                int n  = l >> 2;
                int kq = (l & 3) * 4;
                if (n0 + n < Nn)
                    v = *reinterpret_cast<const float4*>(&B[(size_t)(n0 + n) * Kn + k0 + kq]);
            }
            rb[i] = v;
        }
    };
    auto storeA = [&]() {
#pragma unroll
        for (int i = 0; i < 2; i++) {
            int l = tid + i * 256;
            int row = l >> 2;
            int kq  = (l & 3) * 4;
            As[row * LDA + kq + 0] = f2tf(ra[i].x);
            As[row * LDA + kq + 1] = f2tf(ra[i].y);
            As[row * LDA + kq + 2] = f2tf(ra[i].z);
            As[row * LDA + kq + 3] = f2tf(ra[i].w);
        }
    };
    auto storeB = [&]() {
#pragma unroll
        for (int i = 0; i < 2; i++) {
            int l = tid + i * 256;
            if (!TRANSB) {
                int k  = l >> 5;
                int nq = (l & 31) * 4;
                Bs[k * LDB + nq + 0] = f2tf(rb[i].x);
                Bs[k * LDB + nq + 1] = f2tf(rb[i].y);
                Bs[k * LDB + nq + 2] = f2tf(rb[i].z);
                Bs[k * LDB + nq + 3] = f2tf(rb[i].w);
            } else {
                int n  = l >> 2;
                int kq = (l & 3) * 4;
                Bs[(kq + 0) * LDB + n] = f2tf(rb[i].x);
                Bs[(kq + 1) * LDB + n] = f2tf(rb[i].y);
                Bs[(kq + 2) * LDB + n] = f2tf(rb[i].z);
                Bs[(kq + 3) * LDB + n] = f2tf(rb[i].w);
            }
        }
    };

    loadA(0);
    loadB(0);

    for (int k0 = 0; k0 < Kn; k0 += BK) {
        storeA();
        storeB();
        __syncthreads();
        if (k0 + BK < Kn) { loadA(k0 + BK); loadB(k0 + BK); }

#pragma unroll
        for (int kk = 0; kk < BK; kk += 8) {
            unsigned a[4][4], b[4][2];
#pragma unroll
            for (int tm = 0; tm < 4; tm++) {
                int row = wm + tm * 16 + q;
                a[tm][0] = As[(row)     * LDA + kk + r];
                a[tm][1] = As[(row + 8) * LDA + kk + r];
                a[tm][2] = As[(row)     * LDA + kk + 4 + r];
                a[tm][3] = As[(row + 8) * LDA + kk + 4 + r];
            }
#pragma unroll
            for (int tn = 0; tn < 4; tn++) {
                int col = wn + tn * 8 + q;
                b[tn][0] = Bs[(kk + r)     * LDB + col];
                b[tn][1] = Bs[(kk + 4 + r) * LDB + col];
            }
#pragma unroll
            for (int tm = 0; tm < 4; tm++)
#pragma unroll
                for (int tn = 0; tn < 4; tn++) {
                    asm volatile(
                        "mma.sync.aligned.m16n8k8.row.col.f32.tf32.tf32.f32 "
                        "{%0,%1,%2,%3}, {%4,%5,%6,%7}, {%8,%9}, {%0,%1,%2,%3};"
                        : "+f"(c[tm][tn][0]), "+f"(c[tm][tn][1]),
                          "+f"(c[tm][tn][2]), "+f"(c[tm][tn][3])
                        : "r"(a[tm][0]), "r"(a[tm][1]), "r"(a[tm][2]), "r"(a[tm][3]),
                          "r"(b[tn][0]), "r"(b[tn][1]));
                }
        }
        __syncthreads();
    }

#pragma unroll
    for (int tm = 0; tm < 4; tm++) {
        int row = m0 + wm + tm * 16 + q;
#pragma unroll
        for (int tn = 0; tn < 4; tn++) {
            int col = n0 + wn + tn * 8 + 2 * r;
            if (col >= Nn) continue;
            float v0 = c[tm][tn][0], v1 = c[tm][tn][1];
            float v2 = c[tm][tn][2], v3 = c[tm][tn][3];
            if (BIAS) {
                float bb0 = bias[col], bb1 = bias[col + 1];
                v0 += bb0; v1 += bb1; v2 += bb0; v3 += bb1;
            }
            if (RELU) {
                v0 = fmaxf(v0, 0.f); v1 = fmaxf(v1, 0.f);
                v2 = fmaxf(v2, 0.f); v3 = fmaxf(v3, 0.f);
            }
            if (row < Mn) {
                *reinterpret_cast<float2*>(&C[(size_t)row * Nn + col]) = make_float2(v0, v1);
                if (WBF)
                    *reinterpret_cast<__nv_bfloat162*>(&CB[(size_t)row * Nn + col]) =
                        __floats2bfloat162_rn(v0, v1);
            }
            if (row + 8 < Mn) {
                *reinterpret_cast<float2*>(&C[(size_t)(row + 8) * Nn + col]) = make_float2(v2, v3);
                if (WBF)
                    *reinterpret_cast<__nv_bfloat162*>(&CB[(size_t)(row + 8) * Nn + col]) =
                        __floats2bfloat162_rn(v2, v3);
            }
        }
    }
}

// ---------------- fp32 GEMM for narrow MLP layers (blockIdx.z = g) -----------
template <int BM, int BN, int BK, int TM, int TN, bool BIAS, bool RELU>
__global__ __launch_bounds__((BM / TM) * (BN / TN))
void gemm_kernel(const float* __restrict__ A0, const float* __restrict__ A1,
                 const float* __restrict__ B0, const float* __restrict__ B1,
                 const float* __restrict__ bias0, const float* __restrict__ bias1,
                 float* __restrict__ C0, float* __restrict__ C1,
                 int Mn, int Nn, int Kn) {
    constexpr int THREADS = (BM / TM) * (BN / TN);
    __shared__ float As[BK][BM];
    __shared__ float Bs[BK][BN];
    const int gsel = blockIdx.z;
    const float* A    = gsel ? A1 : A0;
    const float* B    = gsel ? B1 : B0;
    const float* bias = gsel ? bias1 : bias0;
    float*       C    = gsel ? C1 : C0;
    const int tid = threadIdx.x;
    const int tx = tid % (BN / TN);
    const int ty = tid / (BN / TN);
    const int m0 = blockIdx.y * BM;
    const int n0 = blockIdx.x * BN;

    float acc[TM][TN];
#pragma unroll
    for (int i = 0; i < TM; i++)
#pragma unroll
        for (int j = 0; j < TN; j++) acc[i][j] = 0.0f;

    for (int k0 = 0; k0 < Kn; k0 += BK) {
#pragma unroll
        for (int l = tid; l < BM * BK / 4; l += THREADS) {
            int row = l / (BK / 4);
            int kq  = (l % (BK / 4)) * 4;
            float4 v = make_float4(0.f, 0.f, 0.f, 0.f);
            if (m0 + row < Mn)
                v = *reinterpret_cast<const float4*>(&A[(size_t)(m0 + row) * Kn + k0 + kq]);
            As[kq + 0][row] = v.x; As[kq + 1][row] = v.y;
            As[kq + 2][row] = v.z; As[kq + 3][row] = v.w;
        }
#pragma unroll
        for (int l = tid; l < BK * BN / 4; l += THREADS) {
            int kk = l / (BN / 4);
            int nq = (l % (BN / 4)) * 4;
            float4 v = make_float4(0.f, 0.f, 0.f, 0.f);
            if (n0 + nq < Nn)
                v = *reinterpret_cast<const float4*>(&B[(size_t)(k0 + kk) * Nn + n0 + nq]);
            *reinterpret_cast<float4*>(&Bs[kk][nq]) = v;
        }
        __syncthreads();
#pragma unroll
        for (int k = 0; k < BK; k++) {
            float a[TM], b[TN];
#pragma unroll
            for (int i = 0; i < TM; i++) a[i] = As[k][ty * TM + i];
#pragma unroll
            for (int j = 0; j < TN; j++) b[j] = Bs[k][tx * TN + j];
#pragma unroll
            for (int i = 0; i < TM; i++)
#pragma unroll
                for (int j = 0; j < TN; j++) acc[i][j] += a[i] * b[j];
        }
        __syncthreads();
    }
#pragma unroll
    for (int i = 0; i < TM; i++) {
        int m = m0 + ty * TM + i;
        if (m >= Mn) continue;
#pragma unroll
        for (int j = 0; j < TN; j += 4) {
            int n = n0 + tx * TN + j;
            if (n >= Nn) continue;
            float4 v = make_float4(acc[i][j], acc[i][j + 1], acc[i][j + 2], acc[i][j + 3]);
            if (BIAS) {
                v.x += bias[n]; v.y += bias[n + 1]; v.z += bias[n + 2]; v.w += bias[n + 3];
            }
            if (RELU) {
                v.x = fmaxf(v.x, 0.f); v.y = fmaxf(v.y, 0.f);
                v.z = fmaxf(v.z, 0.f); v.w = fmaxf(v.w, 0.f);
            }
            *reinterpret_cast<float4*>(&C[(size_t)m * Nn + n]) = v;
        }
    }
}

// ---------------- host-side orchestration -----------------------------------
extern "C" void kernel_launch(void* const* d_in, const int* in_sizes, int n_in,
                              void* d_out, int out_size) {
    const float* x_in[2]  = { (const float*)d_in[0], (const float*)d_in[1] };
    const float* dmat[2]  = { (const float*)d_in[2], (const float*)d_in[3] };
    const int*   ei[2]    = { (const int*)d_in[4],   (const int*)d_in[5]   };
    const float* W1[2]    = { (const float*)d_in[6],  (const float*)d_in[10] };
    const float* b1[2]    = { (const float*)d_in[7],  (const float*)d_in[11] };
    const float* W2[2]    = { (const float*)d_in[8],  (const float*)d_in[12] };
    const float* b2[2]    = { (const float*)d_in[9],  (const float*)d_in[13] };
    const float* L1w[2]   = { (const float*)d_in[14], (const float*)d_in[20] };
    const float* L1b[2]   = { (const float*)d_in[15], (const float*)d_in[21] };
    const float* L2w[2]   = { (const float*)d_in[16], (const float*)d_in[22] };
    const float* L2b[2]   = { (const float*)d_in[17], (const float*)d_in[23] };
    const float* L3w[2]   = { (const float*)d_in[18], (const float*)d_in[24] };
    const float* L3b[2]   = { (const float*)d_in[19], (const float*)d_in[25] };
    float* out = (float*)d_out;

    float *p_t, *p_h, *p_m1, *p_m2, *p_m3;
    cudaGetSymbolAddress((void**)&p_t,  g_t);
    cudaGetSymbolAddress((void**)&p_h,  g_h);
    cudaGetSymbolAddress((void**)&p_m1, g_m1);
    cudaGetSymbolAddress((void**)&p_m2, g_m2);
    cudaGetSymbolAddress((void**)&p_m3, g_m3);

    float* t[2]  = { p_t,  p_t  + (size_t)N_NODES * F0 };
    float* h[2]  = { p_h,  p_h  + (size_t)N_NODES * F0 };
    float* m1[2] = { p_m1, p_m1 + (size_t)N_NODES * 256 };
    float* m2[2] = { p_m2, p_m2 + (size_t)N_NODES * 128 };
    float* m3[2] = { p_m3, p_m3 + (size_t)N_NODES * 64 };

    const int TB = 256;
    const dim3 gN((N_NODES + TB - 1) / TB, 2);
    const dim3 gE((N_EDGES + TB - 1) / TB, 2);
    const int MB = (N_NODES + 127) / 128;   // 63

    init_kernel<<<gN, TB>>>();
    edge_kernel<<<gE, TB>>>(dmat[0], dmat[1], ei[0], ei[1]);
    dinv_kernel<<<gN, TB>>>();
    coeff_kernel<<<gE, TB>>>(ei[0], ei[1]);
    scan_kernel<<<2, 1024>>>();
    scatter_kernel<<<gE, TB>>>(ei[0], ei[1]);

    // GCN layer 1: t = x @ W1 (fp32 + bf16 copy) ; h = relu(agg(t) + b1)
    tf32_gemm<false, false, false, true><<<dim3(F0 / 128, MB, 2), 256>>>(
        x_in[0], x_in[1], W1[0], W1[1], nullptr, nullptr, t[0], t[1],
        N_NODES, F0, F0);
    aggregate_kernel<<<dim3(N_NODES, 2), 128>>>(t[0], t[1], b1[0], b1[1], h[0], h[1]);

    // GCN layer 2
    tf32_gemm<false, false, false, true><<<dim3(F0 / 128, MB, 2), 256>>>(
        h[0], h[1], W2[0], W2[1], nullptr, nullptr, t[0], t[1],
        N_NODES, F0, F0);
    aggregate_kernel<<<dim3(N_NODES, 2), 128>>>(t[0], t[1], b2[0], b2[1], h[0], h[1]);

    // MLP: L1 tf32 (512->256), L2/L3 fp32
    tf32_gemm<false, true, true, false><<<dim3(256 / 128, MB, 2), 256>>>(
        h[0], h[1], L1w[0], L1w[1], L1b[0], L1b[1], m1[0], m1[1],
        N_NODES, 256, F0);
    gemm_kernel<64, 64, 16, 4, 4, true, true>
        <<<dim3(2, (N_NODES + 63) / 64, 2), 256>>>(
            m1[0], m1[1], L2w[0], L2w[1], L2b[0], L2b[1], m2[0], m2[1],
            N_NODES, 128, 256);
    gemm_kernel<64, 64, 16, 4, 4, true, true>
        <<<dim3(1, (N_NODES + 63) / 64, 2), 256>>>(
            m2[0], m2[1], L3w[0], L3w[1], L3b[0], L3b[1], m3[0], m3[1],
            N_NODES, 64, 128);

    // final (tf32, TRANSB): out = x64_m @ y64_d^T  [8000 x 8000]
    tf32_gemm<true, false, false, false><<<dim3((N_NODES + 127) / 128, MB, 1), 256>>>(
        m3[0], m3[0], m3[1], m3[1], nullptr, nullptr, out, out,
        N_NODES, N_NODES, 64);
}